// round 7
// baseline (speedup 1.0000x reference)
#include <cuda_runtime.h>
#include <cuda_fp16.h>
#include <cstdint>

#define NPOS    2048
#define CIN     256
#define COUT    256
#define BATCH   64
#define TI      4              // positions per CTA
#define KC      16
#define NCHUNK  (CIN / KC)     // 16
#define THREADS 512
#define NSTAGE  4

#define XSTRIDE 48             // 32B data + 16B pad, conflict-free ldmatrix
#define XT_BYTES    (BATCH * XSTRIDE)           // 3072 per pos tile
#define STAGE_BYTES (TI * XT_BYTES)             // 12288
#define XOFF(s, p) ((s) * STAGE_BYTES + (p) * XT_BYTES)
#define SMEM_BYTES  (NSTAGE * STAGE_BYTES)      // 49152 (= 48KB static limit)

static __device__ __forceinline__ uint32_t smem_u32(const void* p) {
    uint32_t a;
    asm("{ .reg .u64 t; cvta.to.shared.u64 t, %1; cvt.u32.u64 %0, t; }"
        : "=r"(a) : "l"(p));
    return a;
}

static __device__ __forceinline__ uint32_t h2pack(float lo, float hi) {
    __half2 h = __floats2half2_rn(lo, hi);
    return *reinterpret_cast<uint32_t*>(&h);
}

static __device__ __forceinline__ void sts16(uint32_t addr, uint16_t v) {
    asm volatile("st.shared.u16 [%0], %1;" :: "r"(addr), "h"(v) : "memory");
}

static __device__ __forceinline__ void ldsm4(uint32_t addr, uint32_t r[4]) {
    asm volatile("ldmatrix.sync.aligned.m8n8.x4.shared.b16 {%0,%1,%2,%3}, [%4];"
                 : "=r"(r[0]), "=r"(r[1]), "=r"(r[2]), "=r"(r[3]) : "r"(addr));
}

static __device__ __forceinline__ void mma16816(float d[4], const uint32_t a[4],
                                                const uint32_t b0, const uint32_t b1) {
    asm volatile(
        "mma.sync.aligned.m16n8k16.row.col.f32.f16.f16.f32 "
        "{%0,%1,%2,%3}, {%4,%5,%6,%7}, {%8,%9}, {%0,%1,%2,%3};"
        : "+f"(d[0]), "+f"(d[1]), "+f"(d[2]), "+f"(d[3])
        : "r"(a[0]), "r"(a[1]), "r"(a[2]), "r"(a[3]), "r"(b0), "r"(b1));
}

// k permutation: physical k (within chunk) 4c+d -> smem halfword slot
static __device__ __forceinline__ int kslot(int kappa) {
    const int c = kappa >> 2, d = kappa & 3;
    return (d < 2) ? (2 * c + d) : (2 * c + d + 6);
}

__global__ __launch_bounds__(THREADS, 1)
void fc_hmma5_kernel(const float* __restrict__ x,     // [B, C_IN, N_POS]
                     const float* __restrict__ W,     // [N_POS, C_OUT, C_IN]
                     const float* __restrict__ bias,  // [N_POS, C_OUT]
                     float* __restrict__ out)         // [B, C_OUT, N_POS]
{
    __shared__ __align__(16) char xs[SMEM_BYTES];
    const uint32_t sb = smem_u32(xs);

    const int tid  = threadIdx.x;
    const int wid  = tid >> 5;
    const int lane = tid & 31;

    const int i0 = (blockIdx.x >> 1) * TI;   // position group
    const int mh = blockIdx.x & 1;           // M half (128 rows)

    const int mg = wid & 7;                  // M group within half (16 rows)
    const int pg = wid >> 3;                 // pos-pair group: {0,1} or {2,3}

    const int row0 = lane >> 2;
    const int kq   = (lane & 3) * 4;

    // W row pointers for this warp's 2 positions
    const float* Wp[2];
#pragma unroll
    for (int lp = 0; lp < 2; ++lp)
        Wp[lp] = W + ((size_t)(i0 + pg * 2 + lp) * COUT + mh * 128 + mg * 16 + row0) * CIN;

    const float* xi = x + i0;

    float acc[2][8][4];
#pragma unroll
    for (int p = 0; p < 2; ++p)
#pragma unroll
        for (int n = 0; n < 8; ++n)
#pragma unroll
            for (int c = 0; c < 4; ++c) acc[p][n][c] = 0.0f;

    const int bj = lane >> 3, br = lane & 7;
    const uint32_t b_off = (uint32_t)(((bj & 2) * 4 + br) * XSTRIDE + ((bj & 1) << 4));

    float4 q[2][2];        // W quads
    float4 xr[2][2];       // x prefetch, depth 2: [set][unit] (4 positions each)

    const float* xaddr[2];
    int xslot[2];
#pragma unroll
    for (int v = 0; v < 2; ++v) {
        const int u = tid + v * THREADS;      // [0,1024): k=u&15, b=u>>4
        const int k = u & 15, b = u >> 4;
        xaddr[v] = xi + (size_t)(b * CIN + k) * NPOS;
        xslot[v] = b * XSTRIDE + kslot(k) * 2;
    }

    auto ldg_w = [&](int kc) {
        const int kb = kc * KC + kq;
#pragma unroll
        for (int lp = 0; lp < 2; ++lp) {
            q[lp][0] = *reinterpret_cast<const float4*>(Wp[lp] + kb);
            q[lp][1] = *reinterpret_cast<const float4*>(Wp[lp] + 8 * CIN + kb);
        }
    };

    auto ldg_x = [&](int kc, int set) {
#pragma unroll
        for (int v = 0; v < 2; ++v)
            xr[set][v] = *reinterpret_cast<const float4*>(xaddr[v] + (size_t)kc * KC * NPOS);
    };

    auto sts_x = [&](int s, int set) {
#pragma unroll
        for (int v = 0; v < 2; ++v) {
            const float f[4] = {xr[set][v].x, xr[set][v].y, xr[set][v].z, xr[set][v].w};
#pragma unroll
            for (int p = 0; p < TI; ++p) {
                const __half h = __float2half_rn(f[p]);
                sts16(sb + XOFF(s, p) + (uint32_t)xslot[v],
                      *reinterpret_cast<const uint16_t*>(&h));
            }
        }
    };

    uint32_t ah[2][4], al[2][4];
    auto cvt_w = [&]() {
#pragma unroll
        for (int lp = 0; lp < 2; ++lp) {
#pragma unroll
            for (int r = 0; r < 2; ++r) {
                const float4 v = q[lp][r];
                const uint32_t h02 = h2pack(v.x, v.y);
                const uint32_t h13 = h2pack(v.z, v.w);
                __half2 hh02 = *reinterpret_cast<const __half2*>(&h02);
                __half2 hh13 = *reinterpret_cast<const __half2*>(&h13);
                ah[lp][r]     = h02;
                ah[lp][r + 2] = h13;
                al[lp][r]     = h2pack(v.x - __low2float(hh02), v.y - __high2float(hh02));
                al[lp][r + 2] = h2pack(v.z - __low2float(hh13), v.w - __high2float(hh13));
            }
        }
    };

    auto compute = [&](int s) {
#pragma unroll
        for (int lp = 0; lp < 2; ++lp) {
            const uint32_t hbase = sb + XOFF(s, pg * 2 + lp) + b_off;
            uint32_t bh[16];
#pragma unroll
            for (int ng = 0; ng < 4; ++ng)
                ldsm4(hbase + (uint32_t)(ng * 16 * XSTRIDE), bh + 4 * ng);
#pragma unroll
            for (int nt = 0; nt < 8; ++nt) {
                const int ng = nt >> 1, t = nt & 1;
                const uint32_t b0 = bh[ng * 4 + t * 2];
                const uint32_t b1 = bh[ng * 4 + t * 2 + 1];
                mma16816(acc[lp][nt], ah[lp], b0, b1);
                mma16816(acc[lp][nt], al[lp], b0, b1);
            }
        }
    };

    // ---- prologue ----
    ldg_w(0);
    ldg_x(0, 0);
    ldg_x(1, 1);
    sts_x(0, 0);
    __syncthreads();

    for (int kc = 0; kc < NCHUNK; ++kc) {
        cvt_w();
        if (kc + 1 < NCHUNK) {
            ldg_w(kc + 1);
            sts_x((kc + 1) & (NSTAGE - 1), (kc + 1) & 1);
        }
        if (kc + 2 < NCHUNK)
            ldg_x(kc + 2, kc & 1);
        compute(kc & (NSTAGE - 1));
        if (kc + 1 < NCHUNK)
            __syncthreads();
    }

    // ---- epilogue: pos-pair exchange through smem, float4 stores along i ----
    __syncthreads();
    float2* ep = reinterpret_cast<float2*>(xs);   // [mg(8)][entry(16)][lane(32)] per round

#pragma unroll
    for (int half = 0; half < 2; ++half) {
        const int o = mh * 128 + mg * 16 + row0 + half * 8;
        const float bvA = bias[(size_t)(i0 + pg * 2 + 0) * COUT + o];
        const float bvB = bias[(size_t)(i0 + pg * 2 + 1) * COUT + o];

        if (pg == 0) {
#pragma unroll
            for (int nt = 0; nt < 8; ++nt)
#pragma unroll
                for (int cc = 0; cc < 2; ++cc) {
                    const int e = nt * 2 + cc;
                    float2 v;
                    v.x = acc[0][nt][half * 2 + cc] + bvA;
                    v.y = acc[1][nt][half * 2 + cc] + bvB;
                    ep[(mg * 16 + e) * 32 + lane] = v;
                }
        }
        __syncthreads();
        if (pg == 1) {
#pragma unroll
            for (int nt = 0; nt < 8; ++nt)
#pragma unroll
                for (int cc = 0; cc < 2; ++cc) {
                    const int e = nt * 2 + cc;
                    const float2 v01 = ep[(mg * 16 + e) * 32 + lane];
                    float4 v;
                    v.x = v01.x;
                    v.y = v01.y;
                    v.z = acc[0][nt][half * 2 + cc] + bvA;
                    v.w = acc[1][nt][half * 2 + cc] + bvB;
                    const int b = nt * 8 + (lane & 3) * 2 + cc;
                    *reinterpret_cast<float4*>(out + (size_t)(b * COUT + o) * NPOS + i0) = v;
                }
        }
        __syncthreads();
    }
}

extern "C" void kernel_launch(void* const* d_in, const int* in_sizes, int n_in,
                              void* d_out, int out_size) {
    const float* x    = (const float*)d_in[0];
    const float* W    = (const float*)d_in[1];
    const float* bias = (const float*)d_in[2];
    float* out        = (float*)d_out;
    (void)in_sizes; (void)n_in; (void)out_size;

    fc_hmma5_kernel<<<(NPOS / TI) * 2, THREADS>>>(x, W, bias, out);
}

// round 8
// speedup vs baseline: 1.1441x; 1.1441x over previous
#include <cuda_runtime.h>
#include <cuda_fp16.h>
#include <cstdint>

#define NPOS    2048
#define CIN     256
#define COUT    256
#define BATCH   64
#define TI      2
#define KC      16
#define NCHUNK  (CIN / KC)     // 16
#define THREADS 512
#define NSTAGE  4

#define XSTRIDE 48             // 32B data + 16B pad, conflict-free ldmatrix
#define XT_BYTES    (BATCH * XSTRIDE)           // 3072 (one pos)
#define STAGE_BYTES (TI * XT_BYTES)             // 6144
#define XOFF(s, p) ((s) * STAGE_BYTES + (p) * XT_BYTES)

static __device__ __forceinline__ uint32_t smem_u32(const void* p) {
    uint32_t a;
    asm("{ .reg .u64 t; cvta.to.shared.u64 t, %1; cvt.u32.u64 %0, t; }"
        : "=r"(a) : "l"(p));
    return a;
}

static __device__ __forceinline__ uint32_t h2pack(float lo, float hi) {
    __half2 h = __floats2half2_rn(lo, hi);
    return *reinterpret_cast<uint32_t*>(&h);
}

static __device__ __forceinline__ void sts16(uint32_t addr, uint16_t v) {
    asm volatile("st.shared.u16 [%0], %1;" :: "r"(addr), "h"(v) : "memory");
}

static __device__ __forceinline__ void ldsm4(uint32_t addr, uint32_t r[4]) {
    asm volatile("ldmatrix.sync.aligned.m8n8.x4.shared.b16 {%0,%1,%2,%3}, [%4];"
                 : "=r"(r[0]), "=r"(r[1]), "=r"(r[2]), "=r"(r[3]) : "r"(addr));
}

static __device__ __forceinline__ void mma16816(float d[4], const uint32_t a[4],
                                                const uint32_t b0, const uint32_t b1) {
    asm volatile(
        "mma.sync.aligned.m16n8k16.row.col.f32.f16.f16.f32 "
        "{%0,%1,%2,%3}, {%4,%5,%6,%7}, {%8,%9}, {%0,%1,%2,%3};"
        : "+f"(d[0]), "+f"(d[1]), "+f"(d[2]), "+f"(d[3])
        : "r"(a[0]), "r"(a[1]), "r"(a[2]), "r"(a[3]), "r"(b0), "r"(b1));
}

// k permutation: physical k (within chunk) 4c+d -> smem halfword slot
//   d<2: 2c+d ; d>=2: 2c+d+6   (matches A-frag quad-load assignment)
static __device__ __forceinline__ int kslot(int kappa) {
    const int c = kappa >> 2, d = kappa & 3;
    return (d < 2) ? (2 * c + d) : (2 * c + d + 6);
}

__global__ __launch_bounds__(THREADS, 1)
void fc_hmma6_kernel(const float* __restrict__ x,     // [B, C_IN, N_POS]
                     const float* __restrict__ W,     // [N_POS, C_OUT, C_IN]
                     const float* __restrict__ bias,  // [N_POS, C_OUT]
                     float* __restrict__ out)         // [B, C_OUT, N_POS]
{
    __shared__ __align__(128) char xs[NSTAGE * STAGE_BYTES];   // 24576 B
    const uint32_t sb = smem_u32(xs);

    const int tid  = threadIdx.x;
    const int wid  = tid >> 5;          // 16 warps, m16-slice each, both positions
    const int lane = tid & 31;
    const int i0   = blockIdx.x * TI;

    const int row0 = lane >> 2;
    const int kq   = (lane & 3) * 4;    // physical k-quad base

    const float* Wp[TI];
#pragma unroll
    for (int p = 0; p < TI; ++p)
        Wp[p] = W + ((size_t)(i0 + p) * COUT + wid * 16 + row0) * CIN;

    const float* xi = x + i0;

    float acc[TI][8][4];
#pragma unroll
    for (int p = 0; p < TI; ++p)
#pragma unroll
        for (int n = 0; n < 8; ++n)
#pragma unroll
            for (int c = 0; c < 4; ++c) acc[p][n][c] = 0.0f;

    const int bj = lane >> 3, br = lane & 7;
    const uint32_t b_off = (uint32_t)(((bj & 2) * 4 + br) * XSTRIDE + ((bj & 1) << 4));

    // prefetch registers
    float4 q[TI][2];        // W quads, depth 1
    float2 xr[2][2];        // x, depth 2 (two chunk sets)

    const float* xaddr[2];
    int xslot[2];
#pragma unroll
    for (int v = 0; v < 2; ++v) {
        const int u = tid + v * THREADS;      // [0,1024): kappa=u&15, b=u>>4
        const int k = u & 15, b = u >> 4;
        xaddr[v] = xi + (size_t)(b * CIN + k) * NPOS;
        xslot[v] = b * XSTRIDE + kslot(k) * 2;
    }

    auto ldg_w = [&](int kc) {
        const int kb = kc * KC + kq;
#pragma unroll
        for (int p = 0; p < TI; ++p) {
            q[p][0] = *reinterpret_cast<const float4*>(Wp[p] + kb);
            q[p][1] = *reinterpret_cast<const float4*>(Wp[p] + 8 * CIN + kb);
        }
    };

    auto ldg_x = [&](int kc, int set) {
#pragma unroll
        for (int v = 0; v < 2; ++v)
            xr[set][v] = *reinterpret_cast<const float2*>(xaddr[v] + (size_t)kc * KC * NPOS);
    };

    auto sts_x = [&](int s, int set) {
#pragma unroll
        for (int v = 0; v < 2; ++v) {
            const float f[2] = {xr[set][v].x, xr[set][v].y};
#pragma unroll
            for (int p = 0; p < TI; ++p) {
                const __half h = __float2half_rn(f[p]);
                sts16(sb + XOFF(s, p) + (uint32_t)xslot[v],
                      *reinterpret_cast<const uint16_t*>(&h));
            }
        }
    };

    uint32_t ah[TI][4], al[TI][4];
    auto cvt_w = [&]() {
#pragma unroll
        for (int p = 0; p < TI; ++p) {
#pragma unroll
            for (int r = 0; r < 2; ++r) {
                const float4 v = q[p][r];
                const uint32_t h02 = h2pack(v.x, v.y);
                const uint32_t h13 = h2pack(v.z, v.w);
                __half2 hh02 = *reinterpret_cast<const __half2*>(&h02);
                __half2 hh13 = *reinterpret_cast<const __half2*>(&h13);
                ah[p][r]     = h02;
                ah[p][r + 2] = h13;
                al[p][r]     = h2pack(v.x - __low2float(hh02), v.y - __high2float(hh02));
                al[p][r + 2] = h2pack(v.z - __low2float(hh13), v.w - __high2float(hh13));
            }
        }
    };

    auto compute = [&](int s) {
#pragma unroll
        for (int p = 0; p < TI; ++p) {
            const uint32_t hbase = sb + XOFF(s, p) + b_off;
            uint32_t bh[16];
#pragma unroll
            for (int ng = 0; ng < 4; ++ng)
                ldsm4(hbase + (uint32_t)(ng * 16 * XSTRIDE), bh + 4 * ng);
            // pass 1: all hi products (distinct accumulators -> no RAW stall)
#pragma unroll
            for (int nt = 0; nt < 8; ++nt) {
                const int ng = nt >> 1, t = nt & 1;
                mma16816(acc[p][nt], ah[p], bh[ng * 4 + t * 2], bh[ng * 4 + t * 2 + 1]);
            }
            // pass 2: all lo products (acc reuse distance = 8 MMAs)
#pragma unroll
            for (int nt = 0; nt < 8; ++nt) {
                const int ng = nt >> 1, t = nt & 1;
                mma16816(acc[p][nt], al[p], bh[ng * 4 + t * 2], bh[ng * 4 + t * 2 + 1]);
            }
        }
    };

    // ---- prologue: fill stage 0, prefetch chunk 1 ----
    ldg_w(0);
    ldg_x(0, 0);
    ldg_x(1, 1);
    sts_x(0, 0);
    __syncthreads();

    for (int kc = 0; kc < NCHUNK; ++kc) {
        cvt_w();                                      // consume q(kc)
        if (kc + 1 < NCHUNK) {
            ldg_w(kc + 1);                            // refill q
            sts_x((kc + 1) & (NSTAGE - 1), (kc + 1) & 1);
        }
        if (kc + 2 < NCHUNK)
            ldg_x(kc + 2, kc & 1);                    // refill freed set
        compute(kc & (NSTAGE - 1));
        if (kc + 1 < NCHUNK)
            __syncthreads();
    }

    // ---- epilogue: float2 stores along i ----
    float* oi = out + i0;
#pragma unroll
    for (int half = 0; half < 2; ++half) {
        const int o = wid * 16 + row0 + half * 8;
        const float bv0 = bias[(size_t)i0 * COUT + o];
        const float bv1 = bias[(size_t)(i0 + 1) * COUT + o];
#pragma unroll
        for (int nt = 0; nt < 8; ++nt) {
#pragma unroll
            for (int cc = 0; cc < 2; ++cc) {
                const int b = nt * 8 + (lane & 3) * 2 + cc;
                const int c = half * 2 + cc;
                float2 v;
                v.x = acc[0][nt][c] + bv0;
                v.y = acc[1][nt][c] + bv1;
                *reinterpret_cast<float2*>(oi + (size_t)(b * COUT + o) * NPOS) = v;
            }
        }
    }
}

extern "C" void kernel_launch(void* const* d_in, const int* in_sizes, int n_in,
                              void* d_out, int out_size) {
    const float* x    = (const float*)d_in[0];
    const float* W    = (const float*)d_in[1];
    const float* bias = (const float*)d_in[2];
    float* out        = (float*)d_out;
    (void)in_sizes; (void)n_in; (void)out_size;

    fc_hmma6_kernel<<<NPOS / TI, THREADS>>>(x, W, bias, out);
}